// round 1
// baseline (speedup 1.0000x reference)
#include <cuda_runtime.h>

#define NN 50000
#define EE 600000
#define PP 100000
#define FD 128

// ---- device scratch (allocation-free rule: __device__ globals) ----
__device__ float g_agg[NN * FD];
__device__ float g_deg[NN];
__device__ float g_h1[NN * FD];
__device__ float g_h2[NN * FD];

// ============================================================================
// Scatter: one warp per edge. agg[dst] += h[src]; deg[dst] += 1 (layer 1 only)
// ============================================================================
__global__ void scatter_kernel(const float* __restrict__ h,
                               const int* __restrict__ src,
                               const int* __restrict__ dst,
                               int addDeg)
{
    int gid  = blockIdx.x * blockDim.x + threadIdx.x;
    int e    = gid >> 5;
    int lane = gid & 31;
    if (e >= EE) return;
    int s = src[e];
    int d = dst[e];
    float4 v = *(const float4*)(h + s * FD + lane * 4);
    float* a = g_agg + d * FD + lane * 4;
    atomicAdd(a + 0, v.x);
    atomicAdd(a + 1, v.y);
    atomicAdd(a + 2, v.z);
    atomicAdd(a + 3, v.w);
    if (addDeg && lane == 0) atomicAdd(g_deg + d, 1.0f);
}

// ============================================================================
// Fused SAGE linear: out = act(x @ Ws + (agg/deg) @ Wn + b)
// Persistent blocks, 512 thr (16 warps), whole [Ws;Wn] (128KB) in smem.
// Each warp: 4 rows, each lane: 4 cols -> 16 accumulators.
// ============================================================================
template <bool RELU>
__global__ void __launch_bounds__(512, 1)
sage_linear_kernel(const float* __restrict__ x,
                   const float* __restrict__ Ws,
                   const float* __restrict__ Wn,
                   const float* __restrict__ b,
                   float* __restrict__ out)
{
    extern __shared__ float sm[];
    float* smW   = sm;                 // [256][128]  (Ws rows 0..127, Wn rows 128..255)
    float* stage = sm + 256 * 128;     // [16 warps][4 rows][256]

    int tid  = threadIdx.x;
    int lane = tid & 31;
    int warp = tid >> 5;

    // load weights (16384 float4 total)
    for (int i = tid; i < (128 * 128) / 4; i += blockDim.x) {
        ((float4*)smW)[i]              = ((const float4*)Ws)[i];
        ((float4*)(smW + 128 * 128))[i] = ((const float4*)Wn)[i];
    }
    __syncthreads();

    float4 bias = *(const float4*)(b + lane * 4);
    float* myStage = stage + warp * (4 * 256);
    const int rowsPerBlock = (blockDim.x >> 5) * 4;   // 64

    for (int base = blockIdx.x * rowsPerBlock + warp * 4; base < NN;
         base += gridDim.x * rowsPerBlock) {
        // ---- stage 4 rows: [x | agg/deg] into 256-wide rows ----
#pragma unroll
        for (int r = 0; r < 4; r++) {
            int row = base + r;
            float4 xv = make_float4(0.f, 0.f, 0.f, 0.f);
            float4 mv = make_float4(0.f, 0.f, 0.f, 0.f);
            if (row < NN) {
                xv = *(const float4*)(x + row * FD + lane * 4);
                float4 av = *(const float4*)(g_agg + row * FD + lane * 4);
                float rd = 1.0f / fmaxf(g_deg[row], 1.0f);
                mv.x = av.x * rd; mv.y = av.y * rd;
                mv.z = av.z * rd; mv.w = av.w * rd;
            }
            *(float4*)(myStage + r * 256 + lane * 4)       = xv;
            *(float4*)(myStage + r * 256 + 128 + lane * 4) = mv;
        }
        __syncwarp();

        float acc[4][4];
#pragma unroll
        for (int r = 0; r < 4; r++)
            acc[r][0] = acc[r][1] = acc[r][2] = acc[r][3] = 0.f;

#pragma unroll 4
        for (int k = 0; k < 256; k++) {
            float4 w = *(const float4*)(smW + k * 128 + lane * 4);
#pragma unroll
            for (int r = 0; r < 4; r++) {
                float xv = myStage[r * 256 + k];
                acc[r][0] = fmaf(xv, w.x, acc[r][0]);
                acc[r][1] = fmaf(xv, w.y, acc[r][1]);
                acc[r][2] = fmaf(xv, w.z, acc[r][2]);
                acc[r][3] = fmaf(xv, w.w, acc[r][3]);
            }
        }

#pragma unroll
        for (int r = 0; r < 4; r++) {
            int row = base + r;
            if (row < NN) {
                float4 o;
                o.x = acc[r][0] + bias.x;
                o.y = acc[r][1] + bias.y;
                o.z = acc[r][2] + bias.z;
                o.w = acc[r][3] + bias.w;
                if (RELU) {
                    o.x = fmaxf(o.x, 0.f); o.y = fmaxf(o.y, 0.f);
                    o.z = fmaxf(o.z, 0.f); o.w = fmaxf(o.w, 0.f);
                }
                *(float4*)(out + row * FD + lane * 4) = o;
            }
        }
        __syncwarp();
    }
}

// ============================================================================
// Fused decoder: rows 0..P-1 = pos pairs, rows P..2P-1 = neg pairs
//   z  = h[s]*h[d]
//   t1 = relu(z  @ Wd1 + bd1)
//   t2 = relu(t1 @ Wd2 + bd2)
//   out[p] = t2 . Wd3 + bd3
// ============================================================================
__global__ void __launch_bounds__(512, 1)
decoder_kernel(const float* __restrict__ h,
               const int* __restrict__ ps, const int* __restrict__ pd,
               const int* __restrict__ ns, const int* __restrict__ nd,
               const float* __restrict__ Wd1, const float* __restrict__ bd1,
               const float* __restrict__ Wd2, const float* __restrict__ bd2,
               const float* __restrict__ Wd3, const float* __restrict__ bd3,
               float* __restrict__ out)
{
    extern __shared__ float sm[];
    float* smW1  = sm;                 // [128][128]
    float* smW2  = sm + 128 * 128;     // [128][128]
    float* stage = sm + 2 * 128 * 128; // [16 warps][4 rows][128]

    int tid  = threadIdx.x;
    int lane = tid & 31;
    int warp = tid >> 5;

    for (int i = tid; i < (128 * 128) / 4; i += blockDim.x) {
        ((float4*)smW1)[i] = ((const float4*)Wd1)[i];
        ((float4*)smW2)[i] = ((const float4*)Wd2)[i];
    }
    __syncthreads();

    float4 b1v = *(const float4*)(bd1 + lane * 4);
    float4 b2v = *(const float4*)(bd2 + lane * 4);
    float4 w3v = *(const float4*)(Wd3 + lane * 4);
    float  b3  = bd3[0];

    float* myStage = stage + warp * (4 * 128);
    const int total = 2 * PP;
    const int rowsPerBlock = (blockDim.x >> 5) * 4;   // 64

    for (int base = blockIdx.x * rowsPerBlock + warp * 4; base < total;
         base += gridDim.x * rowsPerBlock) {
        // ---- stage z = h[s] * h[d] ----
#pragma unroll
        for (int r = 0; r < 4; r++) {
            int p = base + r;
            float4 z = make_float4(0.f, 0.f, 0.f, 0.f);
            if (p < total) {
                int s, d;
                if (p < PP) { s = ps[p]; d = pd[p]; }
                else        { s = ns[p - PP]; d = nd[p - PP]; }
                float4 a = *(const float4*)(h + s * FD + lane * 4);
                float4 c = *(const float4*)(h + d * FD + lane * 4);
                z.x = a.x * c.x; z.y = a.y * c.y;
                z.z = a.z * c.z; z.w = a.w * c.w;
            }
            *(float4*)(myStage + r * 128 + lane * 4) = z;
        }
        __syncwarp();

        // ---- GEMV 1 ----
        float acc[4][4];
#pragma unroll
        for (int r = 0; r < 4; r++)
            acc[r][0] = acc[r][1] = acc[r][2] = acc[r][3] = 0.f;
#pragma unroll 4
        for (int k = 0; k < 128; k++) {
            float4 w = *(const float4*)(smW1 + k * 128 + lane * 4);
#pragma unroll
            for (int r = 0; r < 4; r++) {
                float zv = myStage[r * 128 + k];
                acc[r][0] = fmaf(zv, w.x, acc[r][0]);
                acc[r][1] = fmaf(zv, w.y, acc[r][1]);
                acc[r][2] = fmaf(zv, w.z, acc[r][2]);
                acc[r][3] = fmaf(zv, w.w, acc[r][3]);
            }
        }
        __syncwarp();
        // t1 = relu(acc + b1), restage
#pragma unroll
        for (int r = 0; r < 4; r++) {
            float4 t;
            t.x = fmaxf(acc[r][0] + b1v.x, 0.f);
            t.y = fmaxf(acc[r][1] + b1v.y, 0.f);
            t.z = fmaxf(acc[r][2] + b1v.z, 0.f);
            t.w = fmaxf(acc[r][3] + b1v.w, 0.f);
            *(float4*)(myStage + r * 128 + lane * 4) = t;
        }
        __syncwarp();

        // ---- GEMV 2 ----
#pragma unroll
        for (int r = 0; r < 4; r++)
            acc[r][0] = acc[r][1] = acc[r][2] = acc[r][3] = 0.f;
#pragma unroll 4
        for (int k = 0; k < 128; k++) {
            float4 w = *(const float4*)(smW2 + k * 128 + lane * 4);
#pragma unroll
            for (int r = 0; r < 4; r++) {
                float tv = myStage[r * 128 + k];
                acc[r][0] = fmaf(tv, w.x, acc[r][0]);
                acc[r][1] = fmaf(tv, w.y, acc[r][1]);
                acc[r][2] = fmaf(tv, w.z, acc[r][2]);
                acc[r][3] = fmaf(tv, w.w, acc[r][3]);
            }
        }

        // ---- t2 = relu(acc + b2); out = t2 . Wd3 + bd3 (warp reduce) ----
#pragma unroll
        for (int r = 0; r < 4; r++) {
            float t0 = fmaxf(acc[r][0] + b2v.x, 0.f);
            float t1 = fmaxf(acc[r][1] + b2v.y, 0.f);
            float t2 = fmaxf(acc[r][2] + b2v.z, 0.f);
            float t3 = fmaxf(acc[r][3] + b2v.w, 0.f);
            float partial = t0 * w3v.x + t1 * w3v.y + t2 * w3v.z + t3 * w3v.w;
#pragma unroll
            for (int off = 16; off > 0; off >>= 1)
                partial += __shfl_xor_sync(0xffffffffu, partial, off);
            int p = base + r;
            if (lane == 0 && p < total) out[p] = partial + b3;
        }
        __syncwarp();
    }
}

// ============================================================================
// launch
// ============================================================================
extern "C" void kernel_launch(void* const* d_in, const int* in_sizes, int n_in,
                              void* d_out, int out_size)
{
    const float* x    = (const float*)d_in[0];
    const int*   esrc = (const int*)  d_in[1];
    const int*   edst = (const int*)  d_in[2];
    const int*   ps   = (const int*)  d_in[3];
    const int*   pd   = (const int*)  d_in[4];
    const int*   ns   = (const int*)  d_in[5];
    const int*   nd   = (const int*)  d_in[6];
    const float* Ws1  = (const float*)d_in[7];
    const float* Wn1  = (const float*)d_in[8];
    const float* b1   = (const float*)d_in[9];
    const float* Ws2  = (const float*)d_in[10];
    const float* Wn2  = (const float*)d_in[11];
    const float* b2   = (const float*)d_in[12];
    const float* Wd1  = (const float*)d_in[13];
    const float* bd1  = (const float*)d_in[14];
    const float* Wd2  = (const float*)d_in[15];
    const float* bd2  = (const float*)d_in[16];
    const float* Wd3  = (const float*)d_in[17];
    const float* bd3  = (const float*)d_in[18];
    float* out = (float*)d_out;

    void *aggPtr, *degPtr, *h1Ptr, *h2Ptr;
    cudaGetSymbolAddress(&aggPtr, g_agg);
    cudaGetSymbolAddress(&degPtr, g_deg);
    cudaGetSymbolAddress(&h1Ptr,  g_h1);
    cudaGetSymbolAddress(&h2Ptr,  g_h2);

    int nsm = 148;
    cudaDeviceGetAttribute(&nsm, cudaDevAttrMultiProcessorCount, 0);

    const int SAGE_SMEM = 256 * 128 * 4 + 16 * 4 * 256 * 4;   // 196608 B
    const int DEC_SMEM  = 2 * 128 * 128 * 4 + 16 * 4 * 128 * 4; // 163840 B
    cudaFuncSetAttribute(sage_linear_kernel<true>,
                         cudaFuncAttributeMaxDynamicSharedMemorySize, SAGE_SMEM);
    cudaFuncSetAttribute(sage_linear_kernel<false>,
                         cudaFuncAttributeMaxDynamicSharedMemorySize, SAGE_SMEM);
    cudaFuncSetAttribute(decoder_kernel,
                         cudaFuncAttributeMaxDynamicSharedMemorySize, DEC_SMEM);

    int sblocks = (EE * 32 + 255) / 256;

    // ---- layer 1 ----
    cudaMemsetAsync(aggPtr, 0, sizeof(float) * NN * FD, 0);
    cudaMemsetAsync(degPtr, 0, sizeof(float) * NN, 0);
    scatter_kernel<<<sblocks, 256>>>(x, esrc, edst, 1);
    sage_linear_kernel<true><<<nsm, 512, SAGE_SMEM>>>(x, Ws1, Wn1, b1,
                                                      (float*)h1Ptr);
    // ---- layer 2 (deg unchanged) ----
    cudaMemsetAsync(aggPtr, 0, sizeof(float) * NN * FD, 0);
    scatter_kernel<<<sblocks, 256>>>((const float*)h1Ptr, esrc, edst, 0);
    sage_linear_kernel<false><<<nsm, 512, SAGE_SMEM>>>((const float*)h1Ptr,
                                                       Ws2, Wn2, b2,
                                                       (float*)h2Ptr);
    // ---- decoder (pos + neg fused) ----
    decoder_kernel<<<nsm, 512, DEC_SMEM>>>((const float*)h2Ptr,
                                           ps, pd, ns, nd,
                                           Wd1, bd1, Wd2, bd2, Wd3, bd3, out);
}

// round 2
// speedup vs baseline: 1.4292x; 1.4292x over previous
#include <cuda_runtime.h>

#define NN 50000
#define EE 600000
#define PP 100000
#define FD 128

// ---- device scratch ----
__device__ float g_agg[NN * FD];
__device__ float g_deg[NN];
__device__ float g_h1[NN * FD];
__device__ float g_h2[NN * FD];

// ---- packed f32x2 helpers (Blackwell sm_100+) ----
typedef unsigned long long u64;

__device__ __forceinline__ u64 pack_dup(float a) {
    u64 r;
    asm("mov.b64 %0, {%1, %1};" : "=l"(r) : "f"(a));
    return r;
}
__device__ __forceinline__ void ffma2(u64& d, u64 a, u64 b) {
    asm("fma.rn.f32x2 %0, %1, %2, %0;" : "+l"(d) : "l"(a), "l"(b));
}
__device__ __forceinline__ void unpack2(float& lo, float& hi, u64 v) {
    asm("mov.b64 {%0, %1}, %2;" : "=f"(lo), "=f"(hi) : "l"(v));
}

// ============================================================================
// Scatter: one warp per edge, vector reduction (red.global.add.v4.f32)
// ============================================================================
__global__ void scatter_kernel(const float* __restrict__ h,
                               const int* __restrict__ src,
                               const int* __restrict__ dst,
                               int addDeg)
{
    int gid  = blockIdx.x * blockDim.x + threadIdx.x;
    int e    = gid >> 5;
    int lane = gid & 31;
    if (e >= EE) return;
    int s = src[e];
    int d = dst[e];
    float4 v = *(const float4*)(h + s * FD + lane * 4);
    float* a = g_agg + d * FD + lane * 4;
    asm volatile("red.global.add.v4.f32 [%0], {%1, %2, %3, %4};"
                 :: "l"(a), "f"(v.x), "f"(v.y), "f"(v.z), "f"(v.w)
                 : "memory");
    if (addDeg && lane == 0)
        asm volatile("red.global.add.f32 [%0], %1;"
                     :: "l"(g_deg + d), "f"(1.0f) : "memory");
}

// ============================================================================
// Fused SAGE linear with f32x2 packed FMA
// out = act(x @ Ws + (agg/deg) @ Wn + b)
// ============================================================================
template <bool RELU>
__global__ void __launch_bounds__(512, 1)
sage_linear_kernel(const float* __restrict__ x,
                   const float* __restrict__ Ws,
                   const float* __restrict__ Wn,
                   const float* __restrict__ b,
                   float* __restrict__ out)
{
    extern __shared__ float sm[];
    float* smW   = sm;                 // [256][128]
    float* stage = sm + 256 * 128;     // [16 warps][4 rows][256]

    int tid  = threadIdx.x;
    int lane = tid & 31;
    int warp = tid >> 5;

    for (int i = tid; i < (128 * 128) / 4; i += blockDim.x) {
        ((float4*)smW)[i]               = ((const float4*)Ws)[i];
        ((float4*)(smW + 128 * 128))[i] = ((const float4*)Wn)[i];
    }
    __syncthreads();

    float4 bias = *(const float4*)(b + lane * 4);
    float* myStage = stage + warp * (4 * 256);
    const int rowsPerBlock = (blockDim.x >> 5) * 4;   // 64

    for (int base = blockIdx.x * rowsPerBlock + warp * 4; base < NN;
         base += gridDim.x * rowsPerBlock) {
        // ---- stage 4 rows: [x | agg/deg] ----
#pragma unroll
        for (int r = 0; r < 4; r++) {
            int row = base + r;
            float4 xv = make_float4(0.f, 0.f, 0.f, 0.f);
            float4 mv = make_float4(0.f, 0.f, 0.f, 0.f);
            if (row < NN) {
                xv = *(const float4*)(x + row * FD + lane * 4);
                float4 av = *(const float4*)(g_agg + row * FD + lane * 4);
                float rd = 1.0f / fmaxf(g_deg[row], 1.0f);
                mv.x = av.x * rd; mv.y = av.y * rd;
                mv.z = av.z * rd; mv.w = av.w * rd;
            }
            *(float4*)(myStage + r * 256 + lane * 4)       = xv;
            *(float4*)(myStage + r * 256 + 128 + lane * 4) = mv;
        }
        __syncwarp();

        u64 acc[4][2];
#pragma unroll
        for (int r = 0; r < 4; r++) { acc[r][0] = 0ull; acc[r][1] = 0ull; }

        // k loop in steps of 4: per step 4 LDS128(x) + 4 LDS128(w) + packs + 32 FFMA2
#pragma unroll 2
        for (int k = 0; k < 256; k += 4) {
            float4 xq[4];
#pragma unroll
            for (int r = 0; r < 4; r++)
                xq[r] = *(const float4*)(myStage + r * 256 + k);
#pragma unroll
            for (int kk = 0; kk < 4; kk++) {
                ulonglong2 w = *(const ulonglong2*)(smW + (k + kk) * 128 + lane * 4);
#pragma unroll
                for (int r = 0; r < 4; r++) {
                    float xs = (kk == 0) ? xq[r].x : (kk == 1) ? xq[r].y
                             : (kk == 2) ? xq[r].z : xq[r].w;
                    u64 xx = pack_dup(xs);
                    ffma2(acc[r][0], xx, w.x);
                    ffma2(acc[r][1], xx, w.y);
                }
            }
        }

#pragma unroll
        for (int r = 0; r < 4; r++) {
            int row = base + r;
            if (row < NN) {
                float4 o;
                unpack2(o.x, o.y, acc[r][0]);
                unpack2(o.z, o.w, acc[r][1]);
                o.x += bias.x; o.y += bias.y; o.z += bias.z; o.w += bias.w;
                if (RELU) {
                    o.x = fmaxf(o.x, 0.f); o.y = fmaxf(o.y, 0.f);
                    o.z = fmaxf(o.z, 0.f); o.w = fmaxf(o.w, 0.f);
                }
                *(float4*)(out + row * FD + lane * 4) = o;
            }
        }
        __syncwarp();
    }
}

// ============================================================================
// Fused decoder with f32x2 packed FMA
// ============================================================================
__global__ void __launch_bounds__(512, 1)
decoder_kernel(const float* __restrict__ h,
               const int* __restrict__ ps, const int* __restrict__ pd,
               const int* __restrict__ ns, const int* __restrict__ nd,
               const float* __restrict__ Wd1, const float* __restrict__ bd1,
               const float* __restrict__ Wd2, const float* __restrict__ bd2,
               const float* __restrict__ Wd3, const float* __restrict__ bd3,
               float* __restrict__ out)
{
    extern __shared__ float sm[];
    float* smW1  = sm;                 // [128][128]
    float* smW2  = sm + 128 * 128;     // [128][128]
    float* stage = sm + 2 * 128 * 128; // [16 warps][4 rows][128]

    int tid  = threadIdx.x;
    int lane = tid & 31;
    int warp = tid >> 5;

    for (int i = tid; i < (128 * 128) / 4; i += blockDim.x) {
        ((float4*)smW1)[i] = ((const float4*)Wd1)[i];
        ((float4*)smW2)[i] = ((const float4*)Wd2)[i];
    }
    __syncthreads();

    float4 b1v = *(const float4*)(bd1 + lane * 4);
    float4 b2v = *(const float4*)(bd2 + lane * 4);
    float4 w3v = *(const float4*)(Wd3 + lane * 4);
    float  b3  = bd3[0];

    float* myStage = stage + warp * (4 * 128);
    const int total = 2 * PP;
    const int rowsPerBlock = (blockDim.x >> 5) * 4;   // 64

    for (int base = blockIdx.x * rowsPerBlock + warp * 4; base < total;
         base += gridDim.x * rowsPerBlock) {
        // ---- stage z = h[s] * h[d] ----
#pragma unroll
        for (int r = 0; r < 4; r++) {
            int p = base + r;
            float4 z = make_float4(0.f, 0.f, 0.f, 0.f);
            if (p < total) {
                int s, d;
                if (p < PP) { s = ps[p]; d = pd[p]; }
                else        { s = ns[p - PP]; d = nd[p - PP]; }
                float4 a = *(const float4*)(h + s * FD + lane * 4);
                float4 c = *(const float4*)(h + d * FD + lane * 4);
                z.x = a.x * c.x; z.y = a.y * c.y;
                z.z = a.z * c.z; z.w = a.w * c.w;
            }
            *(float4*)(myStage + r * 128 + lane * 4) = z;
        }
        __syncwarp();

        u64 acc[4][2];

        // ---- GEMV 1 ----
#pragma unroll
        for (int r = 0; r < 4; r++) { acc[r][0] = 0ull; acc[r][1] = 0ull; }
#pragma unroll 2
        for (int k = 0; k < 128; k += 4) {
            float4 zq[4];
#pragma unroll
            for (int r = 0; r < 4; r++)
                zq[r] = *(const float4*)(myStage + r * 128 + k);
#pragma unroll
            for (int kk = 0; kk < 4; kk++) {
                ulonglong2 w = *(const ulonglong2*)(smW1 + (k + kk) * 128 + lane * 4);
#pragma unroll
                for (int r = 0; r < 4; r++) {
                    float zs = (kk == 0) ? zq[r].x : (kk == 1) ? zq[r].y
                             : (kk == 2) ? zq[r].z : zq[r].w;
                    u64 zz = pack_dup(zs);
                    ffma2(acc[r][0], zz, w.x);
                    ffma2(acc[r][1], zz, w.y);
                }
            }
        }
        __syncwarp();
        // t1 = relu(acc + b1), restage
#pragma unroll
        for (int r = 0; r < 4; r++) {
            float4 t;
            unpack2(t.x, t.y, acc[r][0]);
            unpack2(t.z, t.w, acc[r][1]);
            t.x = fmaxf(t.x + b1v.x, 0.f);
            t.y = fmaxf(t.y + b1v.y, 0.f);
            t.z = fmaxf(t.z + b1v.z, 0.f);
            t.w = fmaxf(t.w + b1v.w, 0.f);
            *(float4*)(myStage + r * 128 + lane * 4) = t;
        }
        __syncwarp();

        // ---- GEMV 2 ----
#pragma unroll
        for (int r = 0; r < 4; r++) { acc[r][0] = 0ull; acc[r][1] = 0ull; }
#pragma unroll 2
        for (int k = 0; k < 128; k += 4) {
            float4 zq[4];
#pragma unroll
            for (int r = 0; r < 4; r++)
                zq[r] = *(const float4*)(myStage + r * 128 + k);
#pragma unroll
            for (int kk = 0; kk < 4; kk++) {
                ulonglong2 w = *(const ulonglong2*)(smW2 + (k + kk) * 128 + lane * 4);
#pragma unroll
                for (int r = 0; r < 4; r++) {
                    float zs = (kk == 0) ? zq[r].x : (kk == 1) ? zq[r].y
                             : (kk == 2) ? zq[r].z : zq[r].w;
                    u64 zz = pack_dup(zs);
                    ffma2(acc[r][0], zz, w.x);
                    ffma2(acc[r][1], zz, w.y);
                }
            }
        }

        // ---- out = relu(acc + b2) . Wd3 + bd3 ----
#pragma unroll
        for (int r = 0; r < 4; r++) {
            float t0, t1, t2, t3;
            unpack2(t0, t1, acc[r][0]);
            unpack2(t2, t3, acc[r][1]);
            t0 = fmaxf(t0 + b2v.x, 0.f);
            t1 = fmaxf(t1 + b2v.y, 0.f);
            t2 = fmaxf(t2 + b2v.z, 0.f);
            t3 = fmaxf(t3 + b2v.w, 0.f);
            float partial = t0 * w3v.x + t1 * w3v.y + t2 * w3v.z + t3 * w3v.w;
#pragma unroll
            for (int off = 16; off > 0; off >>= 1)
                partial += __shfl_xor_sync(0xffffffffu, partial, off);
            int p = base + r;
            if (lane == 0 && p < total) out[p] = partial + b3;
        }
        __syncwarp();
    }
}

// ============================================================================
// launch
// ============================================================================
extern "C" void kernel_launch(void* const* d_in, const int* in_sizes, int n_in,
                              void* d_out, int out_size)
{
    const float* x    = (const float*)d_in[0];
    const int*   esrc = (const int*)  d_in[1];
    const int*   edst = (const int*)  d_in[2];
    const int*   ps   = (const int*)  d_in[3];
    const int*   pd   = (const int*)  d_in[4];
    const int*   ns   = (const int*)  d_in[5];
    const int*   nd   = (const int*)  d_in[6];
    const float* Ws1  = (const float*)d_in[7];
    const float* Wn1  = (const float*)d_in[8];
    const float* b1   = (const float*)d_in[9];
    const float* Ws2  = (const float*)d_in[10];
    const float* Wn2  = (const float*)d_in[11];
    const float* b2   = (const float*)d_in[12];
    const float* Wd1  = (const float*)d_in[13];
    const float* bd1  = (const float*)d_in[14];
    const float* Wd2  = (const float*)d_in[15];
    const float* bd2  = (const float*)d_in[16];
    const float* Wd3  = (const float*)d_in[17];
    const float* bd3  = (const float*)d_in[18];
    float* out = (float*)d_out;

    void *aggPtr, *degPtr, *h1Ptr, *h2Ptr;
    cudaGetSymbolAddress(&aggPtr, g_agg);
    cudaGetSymbolAddress(&degPtr, g_deg);
    cudaGetSymbolAddress(&h1Ptr,  g_h1);
    cudaGetSymbolAddress(&h2Ptr,  g_h2);

    int nsm = 148;
    cudaDeviceGetAttribute(&nsm, cudaDevAttrMultiProcessorCount, 0);

    const int SAGE_SMEM = 256 * 128 * 4 + 16 * 4 * 256 * 4;     // 196608 B
    const int DEC_SMEM  = 2 * 128 * 128 * 4 + 16 * 4 * 128 * 4; // 163840 B
    cudaFuncSetAttribute(sage_linear_kernel<true>,
                         cudaFuncAttributeMaxDynamicSharedMemorySize, SAGE_SMEM);
    cudaFuncSetAttribute(sage_linear_kernel<false>,
                         cudaFuncAttributeMaxDynamicSharedMemorySize, SAGE_SMEM);
    cudaFuncSetAttribute(decoder_kernel,
                         cudaFuncAttributeMaxDynamicSharedMemorySize, DEC_SMEM);

    int sblocks = (EE * 32 + 255) / 256;

    // ---- layer 1 ----
    cudaMemsetAsync(aggPtr, 0, sizeof(float) * NN * FD, 0);
    cudaMemsetAsync(degPtr, 0, sizeof(float) * NN, 0);
    scatter_kernel<<<sblocks, 256>>>(x, esrc, edst, 1);
    sage_linear_kernel<true><<<nsm, 512, SAGE_SMEM>>>(x, Ws1, Wn1, b1,
                                                      (float*)h1Ptr);
    // ---- layer 2 ----
    cudaMemsetAsync(aggPtr, 0, sizeof(float) * NN * FD, 0);
    scatter_kernel<<<sblocks, 256>>>((const float*)h1Ptr, esrc, edst, 0);
    sage_linear_kernel<false><<<nsm, 512, SAGE_SMEM>>>((const float*)h1Ptr,
                                                       Ws2, Wn2, b2,
                                                       (float*)h2Ptr);
    // ---- decoder ----
    decoder_kernel<<<nsm, 512, DEC_SMEM>>>((const float*)h2Ptr,
                                           ps, pd, ns, nd,
                                           Wd1, bd1, Wd2, bd2, Wd3, bd3, out);
}